// round 1
// baseline (speedup 1.0000x reference)
#include <cuda_runtime.h>
#include <math.h>

#define N_NODES   20000
#define N_EDGES   320000
#define MUL0      64
#define MUL1      32
#define MUL2      16
#define NODE_DIM  240          // 64 + 3*32 + 5*16
#define NUM_BASIS 16
#define NCH       112          // 64 + 32 + 16 fused channels

// Fused projection matrices: M[b][ch] already includes one_scalar and 1/sqrt(64)
__device__ float g_M[NUM_BASIS * NCH];

// ---------------------------------------------------------------------------
// Kernel 1: precompute fused matrices M0/M1/M2 (tiny, one-shot)
// ---------------------------------------------------------------------------
__global__ void precompute_M(const float* __restrict__ W_rbf,
                             const float* __restrict__ w_expand,
                             const float* __restrict__ b_expand,
                             const float* __restrict__ Wp0,
                             const float* __restrict__ Wp1,
                             const float* __restrict__ Wp2)
{
    int idx = blockIdx.x * blockDim.x + threadIdx.x;
    if (idx >= NUM_BASIS * NCH) return;
    int b  = idx / NCH;
    int ch = idx % NCH;
    const float inv = 0.125f;  // 1/sqrt(64)
    float acc = 0.f;
    if (ch < 64) {
        int d = ch;
        for (int c = 0; c < 64; ++c)
            acc += W_rbf[b * 192 + c] * (w_expand[c] + b_expand[c]) * Wp0[c * 64 + d];
    } else if (ch < 96) {
        int d = ch - 64;
        for (int c = 0; c < 64; ++c)
            acc += W_rbf[b * 192 + 64 + c] * (w_expand[c] + b_expand[c]) * Wp1[c * 32 + d];
    } else {
        int d = ch - 96;
        for (int c = 0; c < 64; ++c)
            acc += W_rbf[b * 192 + 128 + c] * (w_expand[c] + b_expand[c]) * Wp2[c * 16 + d];
    }
    g_M[b * NCH + ch] = acc * inv;
}

// ---------------------------------------------------------------------------
// Kernel 2: initialize node_emb rows: [node_scalar | zeros]
// ---------------------------------------------------------------------------
__global__ void init_nodes(const int*   __restrict__ at_no,
                           const float* __restrict__ W_atom,
                           const float* __restrict__ b_atom,
                           float*       __restrict__ node_emb)
{
    int idx = blockIdx.x * blockDim.x + threadIdx.x;
    if (idx >= N_NODES * NODE_DIM) return;
    int n = idx / NODE_DIM;
    int c = idx - n * NODE_DIM;
    float v = 0.f;
    if (c < MUL0) {
        // 1/sqrt(119)
        v = W_atom[at_no[n] * MUL0 + c] * 0.0916698497028211f + b_atom[c];
    }
    node_emb[idx] = v;
}

// ---------------------------------------------------------------------------
// Vectorized L2 reduction (sm_90+ red.global.add.v4.f32)
// ---------------------------------------------------------------------------
__device__ __forceinline__ void red_add_v4(float* addr, float a, float b, float c, float d)
{
    asm volatile("red.global.add.v4.f32 [%0], {%1,%2,%3,%4};"
                 :: "l"(addr), "f"(a), "f"(b), "f"(c), "f"(d) : "memory");
}

// ---------------------------------------------------------------------------
// Kernel 3: per-edge RBF + RSH + fused projection + scatter-add
// ---------------------------------------------------------------------------
__global__ void __launch_bounds__(256)
edge_kernel(const float* __restrict__ pos,
            const int*   __restrict__ edge_index,
            float*       __restrict__ node_emb,
            float*       __restrict__ rbf_out,
            float*       __restrict__ rsh_out)
{
    __shared__ float sM[NUM_BASIS * NCH];
    for (int i = threadIdx.x; i < NUM_BASIS * NCH; i += blockDim.x)
        sM[i] = g_M[i];
    __syncthreads();

    int e = blockIdx.x * blockDim.x + threadIdx.x;
    if (e >= N_EDGES) return;

    int src = edge_index[e];
    int dst = edge_index[N_EDGES + e];

    const float* Ps = pos + 3 * src;
    const float* Pd = pos + 3 * dst;
    // reference permutes pos columns to [1,2,0] before differencing
    float vx = Pd[1] - Ps[1];
    float vy = Pd[2] - Ps[2];
    float vz = Pd[0] - Ps[0];

    float d2   = vx * vx + vy * vy + vz * vz;
    float dist = sqrtf(d2);
    float dcl  = fmaxf(dist, 1e-8f);
    float uinv = 1.0f / dcl;
    float x = vx * uinv, y = vy * uinv, z = vz * uinv;

    const float s3  = 1.7320508075688772f;
    const float s5  = 2.23606797749979f;
    const float s15 = 3.872983346207417f;

    float sh[9];
    sh[0] = 1.f;
    sh[1] = s3 * x;
    sh[2] = s3 * y;
    sh[3] = s3 * z;
    sh[4] = s15 * x * z;
    sh[5] = s15 * x * y;
    sh[6] = s5 * (y * y - 0.5f * (x * x + z * z));
    sh[7] = s15 * y * z;
    sh[8] = 0.5f * s15 * (z * z - x * x);

    // write rsh (9 floats/edge)
    {
        float* ro = rsh_out + (size_t)e * 9;
        #pragma unroll
        for (int i = 0; i < 9; ++i) ro[i] = sh[i];
    }

    // RBF via Chebyshev recurrence: sin(n*theta), theta = pi*d/5
    float rbf[16];
    bool active = (dcl < 5.0f);
    if (active) {
        float X  = dcl * 0.2f;
        float X2 = X * X;
        float X5 = X2 * X2 * X;
        float fc = 1.0f + X5 * (-21.0f + X * (35.0f - 15.0f * X));
        float theta = 3.14159265358979323846f * X;
        float s1, c1;
        __sincosf(theta, &s1, &c1);          // theta in [0, pi): fast path is accurate enough
        // refine with precise sinf/cosf would cost little; use precise to be safe:
        s1 = sinf(theta); c1 = cosf(theta);
        float two  = 2.0f * c1;
        float pref = 0.6324555320336759f * uinv * fc;  // sqrt(2/5)/d * fc
        float sp = 0.f, s = s1;
        #pragma unroll
        for (int n = 0; n < 16; ++n) {
            rbf[n] = pref * s;
            float sn = two * s - sp;
            sp = s; s = sn;
        }
    } else {
        #pragma unroll
        for (int n = 0; n < 16; ++n) rbf[n] = 0.f;
    }

    // write rbf (16 floats/edge, 16B aligned -> float4)
    {
        float4* ro = (float4*)(rbf_out + (size_t)e * 16);
        #pragma unroll
        for (int q = 0; q < 4; ++q)
            ro[q] = make_float4(rbf[4 * q], rbf[4 * q + 1], rbf[4 * q + 2], rbf[4 * q + 3]);
    }

    if (!active) return;   // zero contribution to aggregation

    float* nrow = node_emb + (size_t)dst * NODE_DIM;

    // ---- path 0: e0 = rbf @ M0  -> cols [0, 64) ----
    #pragma unroll
    for (int g = 0; g < 16; ++g) {
        float a0 = 0.f, a1 = 0.f, a2 = 0.f, a3 = 0.f;
        #pragma unroll
        for (int b = 0; b < 16; ++b) {
            float r = rbf[b];
            const float* m = sM + b * NCH + 4 * g;
            a0 = fmaf(r, m[0], a0);
            a1 = fmaf(r, m[1], a1);
            a2 = fmaf(r, m[2], a2);
            a3 = fmaf(r, m[3], a3);
        }
        red_add_v4(nrow + 4 * g, a0, a1, a2, a3);
    }

    // ---- path 1: t1 = rbf @ M1 (32), e1[d*3+m] = t1[d]*sh1[m] -> cols [64,160) ----
    float t1[32];
    #pragma unroll
    for (int d = 0; d < 32; ++d) {
        float a = 0.f;
        #pragma unroll
        for (int b = 0; b < 16; ++b)
            a = fmaf(rbf[b], sM[b * NCH + 64 + d], a);
        t1[d] = a;
    }
    #pragma unroll
    for (int g = 0; g < 24; ++g) {
        int c0 = 4 * g;
        float v0 = t1[(c0 + 0) / 3] * sh[1 + (c0 + 0) % 3];
        float v1 = t1[(c0 + 1) / 3] * sh[1 + (c0 + 1) % 3];
        float v2 = t1[(c0 + 2) / 3] * sh[1 + (c0 + 2) % 3];
        float v3 = t1[(c0 + 3) / 3] * sh[1 + (c0 + 3) % 3];
        red_add_v4(nrow + 64 + c0, v0, v1, v2, v3);
    }

    // ---- path 2: t2 = rbf @ M2 (16), e2[d*5+m] = t2[d]*sh2[m] -> cols [160,240) ----
    float t2[16];
    #pragma unroll
    for (int d = 0; d < 16; ++d) {
        float a = 0.f;
        #pragma unroll
        for (int b = 0; b < 16; ++b)
            a = fmaf(rbf[b], sM[b * NCH + 96 + d], a);
        t2[d] = a;
    }
    #pragma unroll
    for (int g = 0; g < 20; ++g) {
        int c0 = 4 * g;
        float v0 = t2[(c0 + 0) / 5] * sh[4 + (c0 + 0) % 5];
        float v1 = t2[(c0 + 1) / 5] * sh[4 + (c0 + 1) % 5];
        float v2 = t2[(c0 + 2) / 5] * sh[4 + (c0 + 2) % 5];
        float v3 = t2[(c0 + 3) / 5] * sh[4 + (c0 + 3) % 5];
        red_add_v4(nrow + 160 + c0, v0, v1, v2, v3);
    }
}

// ---------------------------------------------------------------------------
// Launch
// ---------------------------------------------------------------------------
extern "C" void kernel_launch(void* const* d_in, const int* in_sizes, int n_in,
                              void* d_out, int out_size)
{
    const int*   at_no      = (const int*)  d_in[0];
    const float* pos        = (const float*)d_in[1];
    const int*   edge_index = (const int*)  d_in[2];
    const float* W_atom     = (const float*)d_in[3];
    const float* b_atom     = (const float*)d_in[4];
    const float* w_expand   = (const float*)d_in[5];
    const float* b_expand   = (const float*)d_in[6];
    const float* W_rbf      = (const float*)d_in[7];
    const float* Wp0        = (const float*)d_in[8];
    const float* Wp1        = (const float*)d_in[9];
    const float* Wp2        = (const float*)d_in[10];

    float* out      = (float*)d_out;
    float* node_emb = out;                                   // 20000*240
    float* rbf_out  = out + (size_t)N_NODES * NODE_DIM;      // 320000*16
    float* rsh_out  = rbf_out + (size_t)N_EDGES * NUM_BASIS; // 320000*9

    // 1) fuse weights (tiny)
    precompute_M<<<(NUM_BASIS * NCH + 127) / 128, 128>>>(W_rbf, w_expand, b_expand,
                                                         Wp0, Wp1, Wp2);
    // 2) init node accumulator
    {
        int total = N_NODES * NODE_DIM;
        init_nodes<<<(total + 255) / 256, 256>>>(at_no, W_atom, b_atom, node_emb);
    }
    // 3) edge kernel: rbf/rsh outputs + scatter-add
    edge_kernel<<<(N_EDGES + 255) / 256, 256>>>(pos, edge_index,
                                                node_emb, rbf_out, rsh_out);
}